// round 12
// baseline (speedup 1.0000x reference)
#include <cuda_runtime.h>
#include <cuda_fp16.h>
#include <cstdint>

// Sparse BasicBlock via fp16 HMMA (mma.sync, sm_80-compatible path).
// Base = validated Round-10 kernel (rel_err 2.46e-4, 1001us). This round:
// full double-buffering (A and B) enabled by K-chunk 32->16 and a dense
// XOR-swizzled A layout (no pitch padding). FP accumulation order is
// identical to R10 (chunk32 already did two k16 MMA steps in this order).
//   g   = vector * relu(bn1(conv1(x)))   at active pixels, 0 elsewhere
//   out = relu(x + bn2(conv2(g)))        at active pixels, relu(x) elsewhere

namespace {
constexpr int B_ = 32, C_ = 256, H_ = 56, W_ = 56;
constexpr int HW_ = H_ * W_, CHW_ = C_ * HW_;
constexpr float EPS = 1e-5f;

constexpr int KC = 16;                    // K-chunk (ci per iteration)
constexpr int NIT = 9 * (C_ / KC);        // 144 iterations
constexpr int A_TILE = 128 * 32;          // 4096 B: 128 rows x 16 fp16, dense swizzled
constexpr int TILE_BYTES = 2 * A_TILE;    // hi+lo = 8192 B
constexpr int PITCH_B = 272;              // 128 fp16 = 256B + 16B pad
constexpr int B_TILE = KC * PITCH_B;      // 4352 B

// smem offsets: A double (hi+lo each), B double, consts
constexpr int S_A0 = 0;                   // 0..8191
constexpr int S_A1 = TILE_BYTES;          // 8192..16383
constexpr int S_B0 = 2 * TILE_BYTES;      // 16384
constexpr int S_B1 = S_B0 + B_TILE;       // 20736
constexpr int S_SC = S_B1 + B_TILE;       // 25088 (128 f32)
constexpr int S_BI = S_SC + 512;          // 25600
constexpr int S_LIST = S_BI + 512;        // 26112 (128 int)
constexpr int SMEM_BYTES = S_LIST + 512;  // 26624 (< 48K static)
constexpr int LSTRIDE = 3200;
}

__device__ float g_scratch[(size_t)B_ * CHW_];                        // 103 MB
__device__ __align__(16) unsigned char wpack[(size_t)576 * TILE_BYTES]; // 4.7 MB
__device__ int d_cnt[B_];
__device__ int d_list[B_ * LSTRIDE];

// ---------------- helpers ----------------
__device__ __forceinline__ uint32_t smem_u32(const void* p) {
    uint32_t a;
    asm("{ .reg .u64 t; cvta.to.shared.u64 t, %1; cvt.u32.u64 %0, t; }" : "=r"(a) : "l"(p));
    return a;
}
__device__ __forceinline__ void cp_async16(uint32_t s, const void* g) {
    asm volatile("cp.async.cg.shared.global [%0], [%1], 16;" :: "r"(s), "l"(g));
}
__device__ __forceinline__ void cp_commit() {
    asm volatile("cp.async.commit_group;" ::: "memory");
}
template <int N> __device__ __forceinline__ void cp_wait() {
    asm volatile("cp.async.wait_group %0;" :: "n"(N) : "memory");
}
__device__ __forceinline__ void ldsm4(uint32_t* r, uint32_t a) {
    asm volatile("ldmatrix.sync.aligned.m8n8.x4.shared.b16 {%0,%1,%2,%3}, [%4];"
                 : "=r"(r[0]), "=r"(r[1]), "=r"(r[2]), "=r"(r[3]) : "r"(a));
}
__device__ __forceinline__ void ldsm4t(uint32_t* r, uint32_t a) {
    asm volatile("ldmatrix.sync.aligned.m8n8.x4.trans.shared.b16 {%0,%1,%2,%3}, [%4];"
                 : "=r"(r[0]), "=r"(r[1]), "=r"(r[2]), "=r"(r[3]) : "r"(a));
}
__device__ __forceinline__ void mma16816(float* c, const uint32_t* a, const uint32_t* b) {
    asm volatile(
        "mma.sync.aligned.m16n8k16.row.col.f32.f16.f16.f32 "
        "{%0,%1,%2,%3}, {%4,%5,%6,%7}, {%8,%9}, {%0,%1,%2,%3};"
        : "+f"(c[0]), "+f"(c[1]), "+f"(c[2]), "+f"(c[3])
        : "r"(a[0]), "r"(a[1]), "r"(a[2]), "r"(a[3]), "r"(b[0]), "r"(b[1]));
}
// A layout: dense 32B rows, 16B chunk swizzled by bit2 of row (conflict-free
// for ldsm4's 8-row phases: banks (8*row + 4*chunk') mod 32 all distinct).
__device__ __forceinline__ int a_off(int row, int chunk) {
    return row * 32 + ((chunk ^ ((row >> 2) & 1)) << 4);
}
// -----------------------------------------

// Weights [O][I][3][3] fp32 -> per (conv,nh,tap,chunk16) dense swizzled image:
// hi matrix [128 x 32B] then lo, fp16.
__global__ __launch_bounds__(256) void prepack_kernel(const float* __restrict__ w1,
                                                      const float* __restrict__ w2) {
    size_t idx = (size_t)blockIdx.x * 256 + threadIdx.x;   // 576 * 2048
    int tix = (int)(idx >> 11);        // image 0..575
    int e   = (int)(idx & 2047);
    int m = e >> 4, kk = e & 15;
    int chunk = tix & 15, tap = (tix >> 4) % 9;
    int nh = (tix / 144) & 1, conv = tix / 288;
    const float* w = conv ? w2 : w1;
    float v = w[((size_t)(nh * 128 + m) * C_ + (chunk * KC + kk)) * 9 + tap];
    __half h = __float2half(v);
    __half l = __float2half(v - __half2float(h));
    int off = a_off(m, kk >> 3) + (kk & 7) * 2;
    unsigned char* base = wpack + (size_t)tix * TILE_BYTES + off;
    *(__half*)base = h;
    *(__half*)(base + A_TILE) = l;
}

// Active-pixel compaction (list order irrelevant: per-pixel results independent).
__global__ void compact_kernel(const float* __restrict__ mask) {
    int b = blockIdx.x;
    __shared__ int cnt;
    if (threadIdx.x == 0) cnt = 0;
    __syncthreads();
    for (int p = threadIdx.x; p < HW_; p += 256)
        if (mask[(size_t)b * HW_ + p] > 0.5f) {
            int s = atomicAdd(&cnt, 1);
            d_list[b * LSTRIDE + s] = p;
        }
    __syncthreads();
    if (threadIdx.x == 0) d_cnt[b] = cnt;
}

// Inactive pixels: out = relu(x), g_scratch = 0.
__global__ __launch_bounds__(256) void fill_kernel(const float* __restrict__ x,
                                                   const float* __restrict__ mask,
                                                   float* __restrict__ out) {
    int idx = blockIdx.x * 256 + threadIdx.x;     // < CHW_ (3136 * 256 exactly)
    int b = blockIdx.y;
    int p = idx % HW_;
    if (mask[(size_t)b * HW_ + p] < 0.5f) {
        size_t i = (size_t)b * CHW_ + idx;
        out[i] = fmaxf(x[i], 0.f);
        g_scratch[i] = 0.f;
    }
}

// STAGE 1: in = x*mask_dilate -> g_scratch   STAGE 2: in = g_scratch -> out
template <int STAGE>
__global__ __launch_bounds__(256, 2)
void conv_hmma(const float* __restrict__ x, const float* __restrict__ md,
               const float* __restrict__ vec,
               const float* __restrict__ bg, const float* __restrict__ bb,
               const float* __restrict__ bm, const float* __restrict__ bv,
               float* __restrict__ out)
{
    __shared__ __align__(16) unsigned char sm[SMEM_BYTES];
    const uint32_t sb = smem_u32(sm);
    const int t = threadIdx.x, lane = t & 31, wid = t >> 5;
    const int nh = blockIdx.x, blk = blockIdx.y, b = blockIdx.z;
    const int cnt = d_cnt[b];
    const int pixbase = blk * 128;
    if (pixbase >= cnt) return;            // uniform per CTA

    float* scs = (float*)(sm + S_SC);
    float* bis = (float*)(sm + S_BI);
    int* slist = (int*)(sm + S_LIST);
    if (t < 128) {
        int ch = nh * 128 + t;
        float iv = rsqrtf(bv[ch] + EPS) * bg[ch];
        scs[t] = iv;
        bis[t] = bb[ch] - bm[ch] * iv;
        int i0 = pixbase + t;
        slist[t] = (i0 < cnt) ? d_list[b * LSTRIDE + i0] : -1;
    }
    __syncthreads();

    const float* inb = (STAGE == 1) ? x + (size_t)b * CHW_ : g_scratch + (size_t)b * CHW_;
    const float* mdb = (STAGE == 1) ? md + (size_t)b * HW_ : nullptr;

    // B gather geometry: each thread owns one (compacted) pixel pair
    const int pp  = (t & 63) * 2;            // local column pair base
    const int kk0 = t >> 6;                  // 0..3
    const int p0r = slist[pp], p1r = slist[pp + 1];
    const bool pv0 = p0r >= 0, pv1 = p1r >= 0;
    const int p0 = pv0 ? p0r : 0, p1 = pv1 ? p1r : 0;
    const int py0 = p0 / W_, px0 = p0 - py0 * W_;
    const int py1 = p1 / W_, px1 = p1 - py1 * W_;

    // warp tiling: 4 (ch) x 2 (pix)
    const int m0 = (wid & 3) * 32;           // channel row base within 128
    const int n0 = (wid >> 2) * 64;          // pixel col base within 128

    float acc[2][8][4];
#pragma unroll
    for (int mt = 0; mt < 2; ++mt)
#pragma unroll
        for (int nt = 0; nt < 8; ++nt)
#pragma unroll
            for (int q = 0; q < 4; ++q) acc[mt][nt][q] = 0.f;

    const int tixbase = ((STAGE - 1) * 2 + nh) * NIT;

    uint32_t u0[4], u1[4];                   // staged B values (fp16x2 bits)

    auto loadA = [&](int it, int buf) {
        const unsigned char* g = wpack + (size_t)(tixbase + it) * TILE_BYTES;
        uint32_t d = sb + (buf ? S_A1 : S_A0);
#pragma unroll
        for (int i = 0; i < 2; ++i) {
            int off = (t + 256 * i) * 16;
            cp_async16(d + off, g + off);
        }
    };
    auto gatherB = [&](int it) {
        int tap = it >> 4, chunk = it & 15;  // it = tap*16 + chunk
        int ty = tap / 3;
        int dy = ty - 1, dx = tap - ty * 3 - 1;
        int iy0 = py0 + dy, ix0 = px0 + dx;
        int iy1 = py1 + dy, ix1 = px1 + dx;
        bool v0 = pv0 && (unsigned)iy0 < (unsigned)H_ && (unsigned)ix0 < (unsigned)W_;
        bool v1 = pv1 && (unsigned)iy1 < (unsigned)H_ && (unsigned)ix1 < (unsigned)W_;
        int sp0 = v0 ? iy0 * W_ + ix0 : 0;
        int sp1 = v1 ? iy1 * W_ + ix1 : 0;
        float pm0 = 0.f, pm1 = 0.f;
        if (v0) pm0 = (STAGE == 1) ? mdb[sp0] : 1.f;
        if (v1) pm1 = (STAGE == 1) ? mdb[sp1] : 1.f;
#pragma unroll
        for (int i = 0; i < 4; ++i) {
            const float* src = inb + (size_t)(chunk * KC + kk0 + i * 4) * HW_;
            float f0 = v0 ? src[sp0] * pm0 : 0.f;
            float f1 = v1 ? src[sp1] * pm1 : 0.f;
            __half h0 = __float2half(f0), h1 = __float2half(f1);
            u0[i] = __half_as_ushort(h0);
            u1[i] = __half_as_ushort(h1);
        }
    };
    auto stsB = [&](int buf) {
        uint32_t base = (buf ? S_B1 : S_B0);
#pragma unroll
        for (int i = 0; i < 4; ++i) {
            *(uint32_t*)(sm + base + (kk0 + i * 4) * PITCH_B + pp * 2) =
                u0[i] | (u1[i] << 16);
        }
    };
    auto mmaBlock = [&](int buf) {
        uint32_t sA = sb + (buf ? S_A1 : S_A0);
        uint32_t sB = sb + (buf ? S_B1 : S_B0);
        uint32_t ah[2][4], al[2][4];
#pragma unroll
        for (int mt = 0; mt < 2; ++mt) {
            int row = m0 + mt * 16 + (lane & 15);
            uint32_t ao = a_off(row, lane >> 4);
            ldsm4(ah[mt], sA + ao);
            ldsm4(al[mt], sA + A_TILE + ao);
        }
#pragma unroll
        for (int ng = 0; ng < 4; ++ng) {
            int k = lane & 15;
            int ncol = n0 + ng * 16 + ((lane >> 4) << 3);
            uint32_t bo = k * PITCH_B + ncol * 2;
            uint32_t bh[4];
            ldsm4t(bh, sB + bo);
#pragma unroll
            for (int mt = 0; mt < 2; ++mt)
#pragma unroll
                for (int j = 0; j < 2; ++j) {
                    float* c = acc[mt][2 * ng + j];
                    mma16816(c, ah[mt], &bh[2 * j]);
                    mma16816(c, al[mt], &bh[2 * j]);
                }
        }
    };

    // ---- pipeline: 144 iterations, A and B double-buffered.
    // Invariants:
    //  * stsB(it) writes B[buf]; last readers mma(it-2) retired by bar#1(it-1),
    //    which this thread passed (it is beyond bar#2(it-1)).
    //  * loadA(it+1) writes A[buf^1]; readers mma(it-1) retired by bar#1(it).
    //  * cp_wait<1> leaves only A(it+1) outstanding -> A(it) landed;
    //    tail iteration uses cp_wait<0>.
    //  * bar#2 publishes A(it)+B(it) to all warps before mma(it).
    loadA(0, 0);
    cp_commit();
    gatherB(0);
    for (int it = 0; it < NIT; ++it) {
        const int buf = it & 1;
        stsB(buf);
        __syncthreads();              // #1: mma(it-1) reads of A[buf^1],B[buf^1] retired
        if (it < NIT - 1) {
            loadA(it + 1, buf ^ 1);
            cp_commit();
            gatherB(it + 1);          // LDGs overlap wait + MMAs
            cp_wait<1>();             // A(it) landed (A(it+1) may be in flight)
        } else {
            cp_wait<0>();
        }
        __syncthreads();              // #2: A(it)+B(it) visible to all warps
        mmaBlock(buf);
    }

    // ---- epilogue: BN (+relu/vector | +residual/relu); mask==1 on all listed
    // pixels, so the reference's mk multiply is the constant 1 here (exact).
#pragma unroll
    for (int mt = 0; mt < 2; ++mt) {
#pragma unroll
        for (int hr = 0; hr < 2; ++hr) {
            int ml = m0 + mt * 16 + (lane >> 2) + hr * 8;
            int ch = nh * 128 + ml;
            float s  = scs[ml];
            float b2 = bis[ml];
            float vv = (STAGE == 1) ? vec[b * C_ + ch] : 0.f;
            size_t chb = (size_t)b * CHW_ + (size_t)ch * HW_;
#pragma unroll
            for (int nt = 0; nt < 8; ++nt) {
#pragma unroll
                for (int q = 0; q < 2; ++q) {
                    int col = n0 + nt * 8 + (lane & 3) * 2 + q;
                    int p = slist[col];
                    if (p >= 0) {
                        float val = acc[mt][nt][hr * 2 + q] * s + b2;
                        if (STAGE == 1)
                            g_scratch[chb + p] = vv * fmaxf(val, 0.f);
                        else
                            out[chb + p] = fmaxf(x[chb + p] + val, 0.f);
                    }
                }
            }
        }
    }
}

extern "C" void kernel_launch(void* const* d_in, const int* in_sizes, int n_in,
                              void* d_out, int out_size) {
    const float* x    = (const float*)d_in[0];
    const float* mask = (const float*)d_in[1];
    const float* md   = (const float*)d_in[2];
    const float* vec  = (const float*)d_in[3];
    const float* w1   = (const float*)d_in[4];
    const float* g1   = (const float*)d_in[5];
    const float* b1   = (const float*)d_in[6];
    const float* m1   = (const float*)d_in[7];
    const float* v1   = (const float*)d_in[8];
    const float* w2   = (const float*)d_in[9];
    const float* g2   = (const float*)d_in[10];
    const float* b2   = (const float*)d_in[11];
    const float* m2   = (const float*)d_in[12];
    const float* v2   = (const float*)d_in[13];
    float* out = (float*)d_out;

    prepack_kernel<<<4608, 256>>>(w1, w2);          // 576 images * 2048 elems / 256
    compact_kernel<<<B_, 256>>>(mask);
    {
        dim3 g(CHW_ / 256, B_);
        fill_kernel<<<g, 256>>>(x, mask, out);
    }
    dim3 grid(2, 25, B_);                            // half, pixel-block, batch
    conv_hmma<1><<<grid, 256>>>(x, md, vec, g1, b1, m1, v1, nullptr);
    conv_hmma<2><<<grid, 256>>>(x, nullptr, nullptr, g2, b2, m2, v2, out);
}

// round 17
// speedup vs baseline: 1.3156x; 1.3156x over previous
#include <cuda_runtime.h>
#include <cuda_fp16.h>
#include <cstdint>

// Sparse BasicBlock via fp16 HMMA (mma.sync, sm_80-compatible path).
// Base = R10 (1001us, rel_err 2.46e-4). This round: (a) single fp16 A term
// (drop A-lo; error ~sqrt2-2x of R10's B-only 2.46e-4, margin kept), which
// (b) makes room to double-buffer BOTH A and B at the validated KC=32 /
// 72-iteration shape, using R12's correctness-validated pipeline schedule.
// A uses a dense XOR-swizzled layout (64B rows, c ^= (row>>1)&3): conflict-
// free ldsm phases, no pitch padding.
//   g   = vector * relu(bn1(conv1(x)))   at active pixels, 0 elsewhere
//   out = relu(x + bn2(conv2(g)))        at active pixels, relu(x) elsewhere

namespace {
constexpr int B_ = 32, C_ = 256, H_ = 56, W_ = 56;
constexpr int HW_ = H_ * W_, CHW_ = C_ * HW_;
constexpr float EPS = 1e-5f;

constexpr int KC = 32;                    // K-chunk (ci per iteration)
constexpr int NIT = 9 * (C_ / KC);        // 72 iterations
constexpr int A_TILE = 128 * 64;          // 8192 B: 128 rows x 32 fp16, dense swizzled
constexpr int PITCH_B = 272;              // 128 fp16 = 256B + 16B pad
constexpr int B_TILE = KC * PITCH_B;      // 8704 B

// smem offsets: A double, B double, consts
constexpr int S_A0 = 0;                   // 0..8191
constexpr int S_A1 = A_TILE;              // 8192..16383
constexpr int S_B0 = 2 * A_TILE;          // 16384
constexpr int S_B1 = S_B0 + B_TILE;       // 25088
constexpr int S_SC = S_B1 + B_TILE;       // 33792 (128 f32)
constexpr int S_BI = S_SC + 512;          // 34304
constexpr int S_LIST = S_BI + 512;        // 34816 (128 int)
constexpr int SMEM_BYTES = S_LIST + 512;  // 35328 (< 48K static)
constexpr int LSTRIDE = 3200;
}

__device__ float g_scratch[(size_t)B_ * CHW_];                        // 103 MB
__device__ __align__(16) unsigned char wpack[(size_t)288 * A_TILE];   // 2.36 MB
__device__ int d_cnt[B_];
__device__ int d_list[B_ * LSTRIDE];

// ---------------- helpers ----------------
__device__ __forceinline__ uint32_t smem_u32(const void* p) {
    uint32_t a;
    asm("{ .reg .u64 t; cvta.to.shared.u64 t, %1; cvt.u32.u64 %0, t; }" : "=r"(a) : "l"(p));
    return a;
}
__device__ __forceinline__ void cp_async16(uint32_t s, const void* g) {
    asm volatile("cp.async.cg.shared.global [%0], [%1], 16;" :: "r"(s), "l"(g));
}
__device__ __forceinline__ void cp_commit() {
    asm volatile("cp.async.commit_group;" ::: "memory");
}
template <int N> __device__ __forceinline__ void cp_wait() {
    asm volatile("cp.async.wait_group %0;" :: "n"(N) : "memory");
}
__device__ __forceinline__ void ldsm4(uint32_t* r, uint32_t a) {
    asm volatile("ldmatrix.sync.aligned.m8n8.x4.shared.b16 {%0,%1,%2,%3}, [%4];"
                 : "=r"(r[0]), "=r"(r[1]), "=r"(r[2]), "=r"(r[3]) : "r"(a));
}
__device__ __forceinline__ void ldsm4t(uint32_t* r, uint32_t a) {
    asm volatile("ldmatrix.sync.aligned.m8n8.x4.trans.shared.b16 {%0,%1,%2,%3}, [%4];"
                 : "=r"(r[0]), "=r"(r[1]), "=r"(r[2]), "=r"(r[3]) : "r"(a));
}
__device__ __forceinline__ void mma16816(float* c, const uint32_t* a, const uint32_t* b) {
    asm volatile(
        "mma.sync.aligned.m16n8k16.row.col.f32.f16.f16.f32 "
        "{%0,%1,%2,%3}, {%4,%5,%6,%7}, {%8,%9}, {%0,%1,%2,%3};"
        : "+f"(c[0]), "+f"(c[1]), "+f"(c[2]), "+f"(c[3])
        : "r"(a[0]), "r"(a[1]), "r"(a[2]), "r"(a[3]), "r"(b[0]), "r"(b[1]));
}
// A layout: dense 64B rows (4 chunks of 16B), chunk swizzled c ^= (row>>1)&3.
// For every ldsm 8-row phase (rows r0..r0+7, fixed c), banks
// (16*row + 4*c') mod 32 enumerate (row&1, c^((row>>1)&3)) -> all distinct.
__device__ __forceinline__ int a_off(int row, int chunk) {
    return row * 64 + ((chunk ^ ((row >> 1) & 3)) << 4);
}
// -----------------------------------------

// Weights [O][I][3][3] fp32 -> per (conv,nh,tap,chunk32) dense swizzled image:
// single fp16 hi matrix [128 x 64B].
__global__ __launch_bounds__(256) void prepack_kernel(const float* __restrict__ w1,
                                                      const float* __restrict__ w2) {
    size_t idx = (size_t)blockIdx.x * 256 + threadIdx.x;   // 288 * 4096
    int tix = (int)(idx >> 12);        // image 0..287
    int e   = (int)(idx & 4095);
    int m = e >> 5, kk = e & 31;
    int chunk = tix & 7, tap = (tix >> 3) % 9;
    int nh = (tix / 72) & 1, conv = tix / 144;
    const float* w = conv ? w2 : w1;
    float v = w[((size_t)(nh * 128 + m) * C_ + (chunk * KC + kk)) * 9 + tap];
    int off = a_off(m, kk >> 3) + (kk & 7) * 2;
    *(__half*)(wpack + (size_t)tix * A_TILE + off) = __float2half(v);
}

// Active-pixel compaction (list order irrelevant: per-pixel results independent).
__global__ void compact_kernel(const float* __restrict__ mask) {
    int b = blockIdx.x;
    __shared__ int cnt;
    if (threadIdx.x == 0) cnt = 0;
    __syncthreads();
    for (int p = threadIdx.x; p < HW_; p += 256)
        if (mask[(size_t)b * HW_ + p] > 0.5f) {
            int s = atomicAdd(&cnt, 1);
            d_list[b * LSTRIDE + s] = p;
        }
    __syncthreads();
    if (threadIdx.x == 0) d_cnt[b] = cnt;
}

// Inactive pixels: out = relu(x), g_scratch = 0.
__global__ __launch_bounds__(256) void fill_kernel(const float* __restrict__ x,
                                                   const float* __restrict__ mask,
                                                   float* __restrict__ out) {
    int idx = blockIdx.x * 256 + threadIdx.x;     // < CHW_ (3136 * 256 exactly)
    int b = blockIdx.y;
    int p = idx % HW_;
    if (mask[(size_t)b * HW_ + p] < 0.5f) {
        size_t i = (size_t)b * CHW_ + idx;
        out[i] = fmaxf(x[i], 0.f);
        g_scratch[i] = 0.f;
    }
}

// STAGE 1: in = x*mask_dilate -> g_scratch   STAGE 2: in = g_scratch -> out
template <int STAGE>
__global__ __launch_bounds__(256, 2)
void conv_hmma(const float* __restrict__ x, const float* __restrict__ md,
               const float* __restrict__ vec,
               const float* __restrict__ bg, const float* __restrict__ bb,
               const float* __restrict__ bm, const float* __restrict__ bv,
               float* __restrict__ out)
{
    __shared__ __align__(16) unsigned char sm[SMEM_BYTES];
    const uint32_t sb = smem_u32(sm);
    const int t = threadIdx.x, lane = t & 31, wid = t >> 5;
    const int nh = blockIdx.x, blk = blockIdx.y, b = blockIdx.z;
    const int cnt = d_cnt[b];
    const int pixbase = blk * 128;
    if (pixbase >= cnt) return;            // uniform per CTA

    float* scs = (float*)(sm + S_SC);
    float* bis = (float*)(sm + S_BI);
    int* slist = (int*)(sm + S_LIST);
    if (t < 128) {
        int ch = nh * 128 + t;
        float iv = rsqrtf(bv[ch] + EPS) * bg[ch];
        scs[t] = iv;
        bis[t] = bb[ch] - bm[ch] * iv;
        int i0 = pixbase + t;
        slist[t] = (i0 < cnt) ? d_list[b * LSTRIDE + i0] : -1;
    }
    __syncthreads();

    const float* inb = (STAGE == 1) ? x + (size_t)b * CHW_ : g_scratch + (size_t)b * CHW_;
    const float* mdb = (STAGE == 1) ? md + (size_t)b * HW_ : nullptr;

    // B gather geometry: each thread owns one (compacted) pixel pair
    const int pp  = (t & 63) * 2;            // local column pair base
    const int kk0 = t >> 6;                  // 0..3
    const int p0r = slist[pp], p1r = slist[pp + 1];
    const bool pv0 = p0r >= 0, pv1 = p1r >= 0;
    const int p0 = pv0 ? p0r : 0, p1 = pv1 ? p1r : 0;
    const int py0 = p0 / W_, px0 = p0 - py0 * W_;
    const int py1 = p1 / W_, px1 = p1 - py1 * W_;

    // warp tiling: 4 (ch) x 2 (pix)
    const int m0 = (wid & 3) * 32;           // channel row base within 128
    const int n0 = (wid >> 2) * 64;          // pixel col base within 128

    float acc[2][8][4];
#pragma unroll
    for (int mt = 0; mt < 2; ++mt)
#pragma unroll
        for (int nt = 0; nt < 8; ++nt)
#pragma unroll
            for (int q = 0; q < 4; ++q) acc[mt][nt][q] = 0.f;

    const int tixbase = ((STAGE - 1) * 2 + nh) * NIT;

    uint32_t u0[8], u1[8];                   // staged B values (fp16 bits)

    auto loadA = [&](int it, int buf) {
        const unsigned char* g = wpack + (size_t)(tixbase + it) * A_TILE;
        uint32_t d = sb + (buf ? S_A1 : S_A0);
#pragma unroll
        for (int i = 0; i < 2; ++i) {
            int off = (t + 256 * i) * 16;
            cp_async16(d + off, g + off);
        }
    };
    auto gatherB = [&](int it) {
        int tap = it >> 3, chunk = it & 7;   // it = tap*8 + chunk
        int ty = tap / 3;
        int dy = ty - 1, dx = tap - ty * 3 - 1;
        int iy0 = py0 + dy, ix0 = px0 + dx;
        int iy1 = py1 + dy, ix1 = px1 + dx;
        bool v0 = pv0 && (unsigned)iy0 < (unsigned)H_ && (unsigned)ix0 < (unsigned)W_;
        bool v1 = pv1 && (unsigned)iy1 < (unsigned)H_ && (unsigned)ix1 < (unsigned)W_;
        int sp0 = v0 ? iy0 * W_ + ix0 : 0;
        int sp1 = v1 ? iy1 * W_ + ix1 : 0;
        float pm0 = 0.f, pm1 = 0.f;
        if (v0) pm0 = (STAGE == 1) ? mdb[sp0] : 1.f;
        if (v1) pm1 = (STAGE == 1) ? mdb[sp1] : 1.f;
#pragma unroll
        for (int i = 0; i < 8; ++i) {
            const float* src = inb + (size_t)(chunk * KC + kk0 + i * 4) * HW_;
            float f0 = v0 ? src[sp0] * pm0 : 0.f;
            float f1 = v1 ? src[sp1] * pm1 : 0.f;
            u0[i] = __half_as_ushort(__float2half(f0));
            u1[i] = __half_as_ushort(__float2half(f1));
        }
    };
    auto stsB = [&](int buf) {
        uint32_t base = (buf ? S_B1 : S_B0);
#pragma unroll
        for (int i = 0; i < 8; ++i) {
            *(uint32_t*)(sm + base + (kk0 + i * 4) * PITCH_B + pp * 2) =
                u0[i] | (u1[i] << 16);
        }
    };
    auto mmaBlock = [&](int buf) {
        uint32_t sA = sb + (buf ? S_A1 : S_A0);
        uint32_t sB = sb + (buf ? S_B1 : S_B0);
#pragma unroll
        for (int s = 0; s < 2; ++s) {
            uint32_t ah[2][4];
#pragma unroll
            for (int mt = 0; mt < 2; ++mt) {
                int row = m0 + mt * 16 + (lane & 15);
                uint32_t ao = a_off(row, s * 2 + (lane >> 4));
                ldsm4(ah[mt], sA + ao);
            }
#pragma unroll
            for (int ng = 0; ng < 4; ++ng) {
                int k = s * 16 + (lane & 15);
                int ncol = n0 + ng * 16 + ((lane >> 4) << 3);
                uint32_t bo = k * PITCH_B + ncol * 2;
                uint32_t bh[4];
                ldsm4t(bh, sB + bo);
#pragma unroll
                for (int mt = 0; mt < 2; ++mt)
#pragma unroll
                    for (int j = 0; j < 2; ++j)
                        mma16816(acc[mt][2 * ng + j], ah[mt], &bh[2 * j]);
            }
        }
    };

    // ---- pipeline: 72 iterations, A and B double-buffered (R12-validated).
    // Invariants:
    //  * stsB(it) writes B[buf]; last readers mma(it-2) retired by bar#1(it-1).
    //  * loadA(it+1) writes A[buf^1]; readers mma(it-1) retired by bar#1(it).
    //  * cp_wait<1> leaves only A(it+1) outstanding -> A(it) landed;
    //    tail iteration uses cp_wait<0>.
    //  * bar#2 publishes A(it)+B(it) to all warps before mma(it).
    loadA(0, 0);
    cp_commit();
    gatherB(0);
    for (int it = 0; it < NIT; ++it) {
        const int buf = it & 1;
        stsB(buf);
        __syncthreads();              // #1
        if (it < NIT - 1) {
            loadA(it + 1, buf ^ 1);
            cp_commit();
            gatherB(it + 1);          // LDGs overlap wait + MMAs
            cp_wait<1>();
        } else {
            cp_wait<0>();
        }
        __syncthreads();              // #2
        mmaBlock(buf);
    }

    // ---- epilogue: BN (+relu/vector | +residual/relu); mask==1 on all listed
    // pixels, so the reference's mk multiply is the constant 1 here (exact).
#pragma unroll
    for (int mt = 0; mt < 2; ++mt) {
#pragma unroll
        for (int hr = 0; hr < 2; ++hr) {
            int ml = m0 + mt * 16 + (lane >> 2) + hr * 8;
            int ch = nh * 128 + ml;
            float s  = scs[ml];
            float b2 = bis[ml];
            float vv = (STAGE == 1) ? vec[b * C_ + ch] : 0.f;
            size_t chb = (size_t)b * CHW_ + (size_t)ch * HW_;
#pragma unroll
            for (int nt = 0; nt < 8; ++nt) {
#pragma unroll
                for (int q = 0; q < 2; ++q) {
                    int col = n0 + nt * 8 + (lane & 3) * 2 + q;
                    int p = slist[col];
                    if (p >= 0) {
                        float val = acc[mt][nt][hr * 2 + q] * s + b2;
                        if (STAGE == 1)
                            g_scratch[chb + p] = vv * fmaxf(val, 0.f);
                        else
                            out[chb + p] = fmaxf(x[chb + p] + val, 0.f);
                    }
                }
            }
        }
    }
}

extern "C" void kernel_launch(void* const* d_in, const int* in_sizes, int n_in,
                              void* d_out, int out_size) {
    const float* x    = (const float*)d_in[0];
    const float* mask = (const float*)d_in[1];
    const float* md   = (const float*)d_in[2];
    const float* vec  = (const float*)d_in[3];
    const float* w1   = (const float*)d_in[4];
    const float* g1   = (const float*)d_in[5];
    const float* b1   = (const float*)d_in[6];
    const float* m1   = (const float*)d_in[7];
    const float* v1   = (const float*)d_in[8];
    const float* w2   = (const float*)d_in[9];
    const float* g2   = (const float*)d_in[10];
    const float* b2   = (const float*)d_in[11];
    const float* m2   = (const float*)d_in[12];
    const float* v2   = (const float*)d_in[13];
    float* out = (float*)d_out;

    prepack_kernel<<<4608, 256>>>(w1, w2);          // 288 images * 4096 elems / 256
    compact_kernel<<<B_, 256>>>(mask);
    {
        dim3 g(CHW_ / 256, B_);
        fill_kernel<<<g, 256>>>(x, mask, out);
    }
    dim3 grid(2, 25, B_);                            // half, pixel-block, batch
    conv_hmma<1><<<grid, 256>>>(x, md, vec, g1, b1, m1, v1, nullptr);
    conv_hmma<2><<<grid, 256>>>(x, nullptr, nullptr, g2, b2, m2, v2, out);
}